// round 11
// baseline (speedup 1.0000x reference)
#include <cuda_runtime.h>
#include <cuda_bf16.h>
#include <cstdint>

#define N_NODES 100000
#define N_EDGES 1000000
#define D 64
#define CAP 64            // bucket capacity per node (max expected degree ~27)

typedef unsigned long long u64;

// ---------------------------------------------------------------------------
// Scratch. g_count starts zero (device globals zero-init); the fused kernel
// resets it after reading -> invariant: zero between kernel_launch calls.
// ---------------------------------------------------------------------------
__device__ int g_count[N_NODES];
__device__ int g_bucket[N_NODES * CAP];   // 25.6 MB

// ---------------------------------------------------------------------------
// K0: direct bucket fill (no histogram, no scan). 4 edges per thread.
// ---------------------------------------------------------------------------
__global__ void fill_kernel(const int4* __restrict__ src4,
                            const int4* __restrict__ dst4,
                            int* __restrict__ cnt,
                            int* __restrict__ bucket) {
    int t = blockIdx.x * blockDim.x + threadIdx.x;
    if (t >= N_EDGES / 4) return;
    int4 s = src4[t];
    int4 d = dst4[t];
    if ((unsigned)s.x < N_NODES && (unsigned)d.x < N_NODES) {
        int p = atomicAdd(&cnt[d.x], 1);
        if (p < CAP) bucket[d.x * CAP + p] = s.x;
    }
    if ((unsigned)s.y < N_NODES && (unsigned)d.y < N_NODES) {
        int p = atomicAdd(&cnt[d.y], 1);
        if (p < CAP) bucket[d.y * CAP + p] = s.y;
    }
    if ((unsigned)s.z < N_NODES && (unsigned)d.z < N_NODES) {
        int p = atomicAdd(&cnt[d.z], 1);
        if (p < CAP) bucket[d.z * CAP + p] = s.z;
    }
    if ((unsigned)s.w < N_NODES && (unsigned)d.w < N_NODES) {
        int p = atomicAdd(&cnt[d.w], 1);
        if (p < CAP) bucket[d.w * CAP + p] = s.w;
    }
}

// ---------------------------------------------------------------------------
// K1: fused gather + (1+eps)*x + 2-layer MLP.
// Block = 64 nodes, 256 threads.
//  Phase A (gather): 8 warps x 8 nodes; lane owns a float2 of the row;
//    neighbor indices fetched coalesced + shfl-broadcast; result written
//    straight into the Xs smem tile. cnt reset to keep zero-invariant.
//  Phase B (MLP): thread tile 2 rows x 8 cols, cols {4cg..} U {32+4cg..}
//    -> conflict-free weight LDS.128 and x broadcasts; fma.rn.f32x2.
// ---------------------------------------------------------------------------
#define MLP_ROWS 64
#define XS_STRIDE 66

__device__ __forceinline__ float leaky(float v) {
    return fmaxf(v, 0.01f * v);
}

#define FMA2(dd, a, b, c) \
    asm("fma.rn.f32x2 %0, %1, %2, %3;" : "=l"(dd) : "l"(a), "l"(b), "l"(c))
#define PACK_DUP(out, f) \
    asm("mov.b64 %0, {%1, %1};" : "=l"(out) : "r"(__float_as_uint(f)))
#define PACK2F(out, lo, hi) \
    asm("mov.b64 %0, {%1, %2};" : "=l"(out) : "r"(__float_as_uint(lo)), "r"(__float_as_uint(hi)))
#define UNPACK2F(lo, hi, in) \
    { unsigned _l, _h; asm("mov.b64 {%0, %1}, %2;" : "=r"(_l), "=r"(_h) : "l"(in)); \
      lo = __uint_as_float(_l); hi = __uint_as_float(_h); }

__global__ __launch_bounds__(256)
void fused_kernel(const float2* __restrict__ x2,
                  const float* __restrict__ eps,
                  int* __restrict__ cnt,
                  const int* __restrict__ bucket,
                  const float* __restrict__ W1, const float* __restrict__ b1,
                  const float* __restrict__ W2, const float* __restrict__ b2,
                  float* __restrict__ out) {
    __shared__ float Xs[MLP_ROWS][XS_STRIDE];   // 16.9 KB
    __shared__ float Ws[D][D];                  // 16 KB
    __shared__ float bs[D];

    const int tid  = threadIdx.x;
    const int wrp  = tid >> 5;          // 0..7
    const int lane = tid & 31;
    const int row_base = blockIdx.x * MLP_ROWS;

    // --- kick off W1/b1 loads (independent of gather) ---
    {
        const float4* w = (const float4*)W1;
        float4* ws = (float4*)&Ws[0][0];
        for (int idx = tid; idx < D * D / 4; idx += 256) ws[idx] = w[idx];
        if (tid < D) bs[tid] = b1[tid];
    }

    // --- Phase A: gather 8 nodes per warp into Xs ---
    {
        float s = 1.0f + *eps;
        for (int q = 0; q < 8; q++) {
            int r = wrp * 8 + q;
            int node = row_base + r;
            float ax = 0.f, ay = 0.f;
            if (node < N_NODES) {
                int deg = min(cnt[node], CAP);
                if (lane == 0) cnt[node] = 0;        // restore zero-invariant
                float2 v = x2[(unsigned)node * 32u + lane];
                ax = s * v.x; ay = s * v.y;
                const int* brow = bucket + node * CAP;
                for (int b = 0; b < deg; b += 32) {
                    int n = min(32, deg - b);
                    int myidx = (lane < n) ? brow[b + lane] : 0;
                    for (int j = 0; j < n; j += 4) {
                        int s0 = __shfl_sync(0xffffffffu, myidx, j);
                        int s1 = __shfl_sync(0xffffffffu, myidx, j + 1);
                        int s2 = __shfl_sync(0xffffffffu, myidx, j + 2);
                        int s3 = __shfl_sync(0xffffffffu, myidx, j + 3);
                        float2 n0 = x2[(unsigned)s0 * 32u + lane];
                        float2 n1 = x2[(unsigned)s1 * 32u + lane];
                        float2 n2 = x2[(unsigned)s2 * 32u + lane];
                        float2 n3 = x2[(unsigned)s3 * 32u + lane];
                        ax += n0.x; ay += n0.y;
                        if (j + 1 < n) { ax += n1.x; ay += n1.y; }
                        if (j + 2 < n) { ax += n2.x; ay += n2.y; }
                        if (j + 3 < n) { ax += n3.x; ay += n3.y; }
                    }
                }
            }
            *(float2*)&Xs[r][2 * lane] = make_float2(ax, ay);
        }
    }
    __syncthreads();

    // --- Phase B: MLP. 2 rows x 8 cols per thread. ---
    const int cg = tid & 7;
    const int rg = tid >> 3;            // 0..31
    const int r0 = rg * 2;
    const int ca = cg * 4;
    const int cb = 32 + cg * 4;

    u64 acc[2][4];
    {
        u64 a0, a1, b0, b1p;
        PACK2F(a0, bs[ca],     bs[ca + 1]);
        PACK2F(a1, bs[ca + 2], bs[ca + 3]);
        PACK2F(b0, bs[cb],     bs[cb + 1]);
        PACK2F(b1p, bs[cb + 2], bs[cb + 3]);
        acc[0][0] = a0; acc[0][1] = a1; acc[0][2] = b0; acc[0][3] = b1p;
        acc[1][0] = a0; acc[1][1] = a1; acc[1][2] = b0; acc[1][3] = b1p;
    }

    #pragma unroll 4
    for (int k = 0; k < D; k++) {
        ulonglong2 wa = *(const ulonglong2*)&Ws[k][ca];
        ulonglong2 wb = *(const ulonglong2*)&Ws[k][cb];
        #pragma unroll
        for (int i = 0; i < 2; i++) {
            u64 xx; PACK_DUP(xx, Xs[r0 + i][k]);
            FMA2(acc[i][0], xx, wa.x, acc[i][0]);
            FMA2(acc[i][1], xx, wa.y, acc[i][1]);
            FMA2(acc[i][2], xx, wb.x, acc[i][2]);
            FMA2(acc[i][3], xx, wb.y, acc[i][3]);
        }
    }
    __syncthreads();

    // leaky + write back into Xs
    #pragma unroll
    for (int i = 0; i < 2; i++) {
        float lo, hi;
        UNPACK2F(lo, hi, acc[i][0]); Xs[r0 + i][ca]     = leaky(lo); Xs[r0 + i][ca + 1] = leaky(hi);
        UNPACK2F(lo, hi, acc[i][1]); Xs[r0 + i][ca + 2] = leaky(lo); Xs[r0 + i][ca + 3] = leaky(hi);
        UNPACK2F(lo, hi, acc[i][2]); Xs[r0 + i][cb]     = leaky(lo); Xs[r0 + i][cb + 1] = leaky(hi);
        UNPACK2F(lo, hi, acc[i][3]); Xs[r0 + i][cb + 2] = leaky(lo); Xs[r0 + i][cb + 3] = leaky(hi);
    }

    // load W2, b2
    {
        const float4* w = (const float4*)W2;
        float4* ws = (float4*)&Ws[0][0];
        for (int idx = tid; idx < D * D / 4; idx += 256) ws[idx] = w[idx];
        if (tid < D) bs[tid] = b2[tid];
    }
    __syncthreads();

    {
        u64 a0, a1, b0, b1p;
        PACK2F(a0, bs[ca],     bs[ca + 1]);
        PACK2F(a1, bs[ca + 2], bs[ca + 3]);
        PACK2F(b0, bs[cb],     bs[cb + 1]);
        PACK2F(b1p, bs[cb + 2], bs[cb + 3]);
        acc[0][0] = a0; acc[0][1] = a1; acc[0][2] = b0; acc[0][3] = b1p;
        acc[1][0] = a0; acc[1][1] = a1; acc[1][2] = b0; acc[1][3] = b1p;
    }

    #pragma unroll 4
    for (int k = 0; k < D; k++) {
        ulonglong2 wa = *(const ulonglong2*)&Ws[k][ca];
        ulonglong2 wb = *(const ulonglong2*)&Ws[k][cb];
        #pragma unroll
        for (int i = 0; i < 2; i++) {
            u64 xx; PACK_DUP(xx, Xs[r0 + i][k]);
            FMA2(acc[i][0], xx, wa.x, acc[i][0]);
            FMA2(acc[i][1], xx, wa.y, acc[i][1]);
            FMA2(acc[i][2], xx, wb.x, acc[i][2]);
            FMA2(acc[i][3], xx, wb.y, acc[i][3]);
        }
    }

    #pragma unroll
    for (int i = 0; i < 2; i++) {
        int row = row_base + r0 + i;
        if (row < N_NODES) {
            float lo, hi;
            float4 va, vb;
            UNPACK2F(lo, hi, acc[i][0]); va.x = leaky(lo); va.y = leaky(hi);
            UNPACK2F(lo, hi, acc[i][1]); va.z = leaky(lo); va.w = leaky(hi);
            UNPACK2F(lo, hi, acc[i][2]); vb.x = leaky(lo); vb.y = leaky(hi);
            UNPACK2F(lo, hi, acc[i][3]); vb.z = leaky(lo); vb.w = leaky(hi);
            *(float4*)(out + (long long)row * D + ca) = va;
            *(float4*)(out + (long long)row * D + cb) = vb;
        }
    }
}

// ---------------------------------------------------------------------------
// launch — 2 kernels total
// ---------------------------------------------------------------------------
extern "C" void kernel_launch(void* const* d_in, const int* in_sizes, int n_in,
                              void* d_out, int out_size) {
    const float* x   = (const float*)d_in[0];
    const int*   ei  = (const int*)d_in[1];      // int32 (JAX downcasts int64)
    const float* eps = (const float*)d_in[2];
    const float* W1  = (const float*)d_in[3];
    const float* b1  = (const float*)d_in[4];
    const float* W2  = (const float*)d_in[5];
    const float* b2  = (const float*)d_in[6];
    float* out = (float*)d_out;

    int* cnt;    cudaGetSymbolAddress((void**)&cnt,    g_count);
    int* bucket; cudaGetSymbolAddress((void**)&bucket, g_bucket);

    const int4* src4 = (const int4*)ei;
    const int4* dst4 = (const int4*)(ei + N_EDGES);
    const int EQ = N_EDGES / 4;

    fill_kernel<<<(EQ + 255) / 256, 256>>>(src4, dst4, cnt, bucket);      // #0
    fused_kernel<<<(N_NODES + MLP_ROWS - 1) / MLP_ROWS, 256>>>(           // #1
        (const float2*)x, eps, cnt, bucket, W1, b1, W2, b2, out);
}

// round 12
// speedup vs baseline: 1.2689x; 1.2689x over previous
#include <cuda_runtime.h>
#include <cuda_bf16.h>
#include <cstdint>

#define N_NODES 100000
#define N_EDGES 1000000
#define D 64
#define CAP 64            // bucket capacity per node (max expected degree ~27)

typedef unsigned long long u64;

// ---------------------------------------------------------------------------
// Scratch. g_count starts zero (device globals zero-init); gather resets it
// after reading -> invariant: zero between kernel_launch calls.
// ---------------------------------------------------------------------------
__device__ float g_agg[N_NODES * D];
__device__ int   g_count[N_NODES];
__device__ int   g_bucket[N_NODES * CAP];   // 25.6 MB

// ---------------------------------------------------------------------------
// K0: direct bucket fill (replaces hist+scan+fill). 4 edges per thread.
// ---------------------------------------------------------------------------
__global__ void fill_kernel(const int4* __restrict__ src4,
                            const int4* __restrict__ dst4,
                            int* __restrict__ cnt,
                            int* __restrict__ bucket) {
    int t = blockIdx.x * blockDim.x + threadIdx.x;
    if (t >= N_EDGES / 4) return;
    int4 s = src4[t];
    int4 d = dst4[t];
    if ((unsigned)s.x < N_NODES && (unsigned)d.x < N_NODES) {
        int p = atomicAdd(&cnt[d.x], 1);
        if (p < CAP) bucket[d.x * CAP + p] = s.x;
    }
    if ((unsigned)s.y < N_NODES && (unsigned)d.y < N_NODES) {
        int p = atomicAdd(&cnt[d.y], 1);
        if (p < CAP) bucket[d.y * CAP + p] = s.y;
    }
    if ((unsigned)s.z < N_NODES && (unsigned)d.z < N_NODES) {
        int p = atomicAdd(&cnt[d.z], 1);
        if (p < CAP) bucket[d.z * CAP + p] = s.z;
    }
    if ((unsigned)s.w < N_NODES && (unsigned)d.w < N_NODES) {
        int p = atomicAdd(&cnt[d.w], 1);
        if (p < CAP) bucket[d.w * CAP + p] = s.w;
    }
}

// ---------------------------------------------------------------------------
// K1: gather + fused (1+eps)*x. One warp per node (100k warps — full MLP),
// lane owns a float2; coalesced index fetch + shfl broadcast.
// Structure identical to the measured-32us R6/R7 gather, reading buckets.
// ---------------------------------------------------------------------------
__global__ __launch_bounds__(256)
void gather_kernel(const float2* __restrict__ x2,
                   const float* __restrict__ eps,
                   int* __restrict__ cnt,
                   const int* __restrict__ bucket,
                   float2* __restrict__ agg2) {
    int warp = (blockIdx.x * blockDim.x + threadIdx.x) >> 5;
    int lane = threadIdx.x & 31;
    if (warp >= N_NODES) return;

    float s = 1.0f + *eps;
    unsigned self = (unsigned)warp * 32u + (unsigned)lane;
    float2 v = x2[self];
    float ax = s * v.x, ay = s * v.y;

    int deg = min(cnt[warp], CAP);
    if (lane == 0) cnt[warp] = 0;          // restore zero-invariant
    const int* brow = bucket + warp * CAP;

    for (int b = 0; b < deg; b += 32) {
        int n = min(32, deg - b);
        int myidx = (lane < n) ? brow[b + lane] : 0;
        for (int j = 0; j < n; j += 4) {
            int s0 = __shfl_sync(0xffffffffu, myidx, j);
            int s1 = __shfl_sync(0xffffffffu, myidx, j + 1);
            int s2 = __shfl_sync(0xffffffffu, myidx, j + 2);
            int s3 = __shfl_sync(0xffffffffu, myidx, j + 3);
            float2 n0 = x2[(unsigned)s0 * 32u + lane];
            float2 n1 = x2[(unsigned)s1 * 32u + lane];
            float2 n2 = x2[(unsigned)s2 * 32u + lane];
            float2 n3 = x2[(unsigned)s3 * 32u + lane];
            ax += n0.x; ay += n0.y;
            if (j + 1 < n) { ax += n1.x; ay += n1.y; }
            if (j + 2 < n) { ax += n2.x; ay += n2.y; }
            if (j + 3 < n) { ax += n3.x; ay += n3.y; }
        }
    }
    float2 o; o.x = ax; o.y = ay;
    agg2[self] = o;
}

// ---------------------------------------------------------------------------
// K2: fused 2-layer MLP (unchanged from R7/R8 — conflict-free quads, FMA2)
// ---------------------------------------------------------------------------
#define MLP_ROWS 64
#define MLP_THREADS 128
#define XS_STRIDE 66

__device__ __forceinline__ float leaky(float v) {
    return fmaxf(v, 0.01f * v);
}

#define FMA2(dd, a, b, c) \
    asm("fma.rn.f32x2 %0, %1, %2, %3;" : "=l"(dd) : "l"(a), "l"(b), "l"(c))
#define PACK_DUP(out, f) \
    asm("mov.b64 %0, {%1, %1};" : "=l"(out) : "r"(__float_as_uint(f)))
#define PACK2F(out, lo, hi) \
    asm("mov.b64 %0, {%1, %2};" : "=l"(out) : "r"(__float_as_uint(lo)), "r"(__float_as_uint(hi)))
#define UNPACK2F(lo, hi, in) \
    { unsigned _l, _h; asm("mov.b64 {%0, %1}, %2;" : "=r"(_l), "=r"(_h) : "l"(in)); \
      lo = __uint_as_float(_l); hi = __uint_as_float(_h); }

__global__ __launch_bounds__(MLP_THREADS)
void mlp_kernel(const float* __restrict__ agg,
                const float* __restrict__ W1, const float* __restrict__ b1,
                const float* __restrict__ W2, const float* __restrict__ b2,
                float* __restrict__ out) {
    __shared__ float Xs[MLP_ROWS][XS_STRIDE];
    __shared__ float Ws[D][D];
    __shared__ float bs[D];

    const int tid = threadIdx.x;
    const int cg  = tid & 7;
    const int rg  = tid >> 3;
    const int row_base = blockIdx.x * MLP_ROWS;
    const int r0 = rg * 4;
    const int ca = cg * 4;
    const int cb = 32 + cg * 4;

    {
        const float2* src = (const float2*)(agg + (long long)row_base * D);
        for (int idx = tid; idx < MLP_ROWS * (D / 2); idx += MLP_THREADS) {
            int r = idx >> 5;
            int p = idx & 31;
            float2 v;
            if (row_base + r < N_NODES) v = src[r * 32 + p];
            else { v.x = 0.f; v.y = 0.f; }
            Xs[r][p * 2]     = v.x;
            Xs[r][p * 2 + 1] = v.y;
        }
    }
    {
        const float4* w = (const float4*)W1;
        float4* ws = (float4*)&Ws[0][0];
        for (int idx = tid; idx < D * D / 4; idx += MLP_THREADS) ws[idx] = w[idx];
        if (tid < D) bs[tid] = b1[tid];
    }
    __syncthreads();

    u64 acc[4][4];
    {
        u64 a0, a1, b0, b1p;
        PACK2F(a0, bs[ca],     bs[ca + 1]);
        PACK2F(a1, bs[ca + 2], bs[ca + 3]);
        PACK2F(b0, bs[cb],     bs[cb + 1]);
        PACK2F(b1p, bs[cb + 2], bs[cb + 3]);
        #pragma unroll
        for (int i = 0; i < 4; i++) {
            acc[i][0] = a0; acc[i][1] = a1; acc[i][2] = b0; acc[i][3] = b1p;
        }
    }

    #pragma unroll 4
    for (int k = 0; k < D; k++) {
        ulonglong2 wa = *(const ulonglong2*)&Ws[k][ca];
        ulonglong2 wb = *(const ulonglong2*)&Ws[k][cb];
        #pragma unroll
        for (int i = 0; i < 4; i++) {
            u64 xx; PACK_DUP(xx, Xs[r0 + i][k]);
            FMA2(acc[i][0], xx, wa.x, acc[i][0]);
            FMA2(acc[i][1], xx, wa.y, acc[i][1]);
            FMA2(acc[i][2], xx, wb.x, acc[i][2]);
            FMA2(acc[i][3], xx, wb.y, acc[i][3]);
        }
    }
    __syncthreads();

    #pragma unroll
    for (int i = 0; i < 4; i++) {
        float lo, hi;
        UNPACK2F(lo, hi, acc[i][0]); Xs[r0 + i][ca]     = leaky(lo); Xs[r0 + i][ca + 1] = leaky(hi);
        UNPACK2F(lo, hi, acc[i][1]); Xs[r0 + i][ca + 2] = leaky(lo); Xs[r0 + i][ca + 3] = leaky(hi);
        UNPACK2F(lo, hi, acc[i][2]); Xs[r0 + i][cb]     = leaky(lo); Xs[r0 + i][cb + 1] = leaky(hi);
        UNPACK2F(lo, hi, acc[i][3]); Xs[r0 + i][cb + 2] = leaky(lo); Xs[r0 + i][cb + 3] = leaky(hi);
    }

    {
        const float4* w = (const float4*)W2;
        float4* ws = (float4*)&Ws[0][0];
        for (int idx = tid; idx < D * D / 4; idx += MLP_THREADS) ws[idx] = w[idx];
        if (tid < D) bs[tid] = b2[tid];
    }
    __syncthreads();

    {
        u64 a0, a1, b0, b1p;
        PACK2F(a0, bs[ca],     bs[ca + 1]);
        PACK2F(a1, bs[ca + 2], bs[ca + 3]);
        PACK2F(b0, bs[cb],     bs[cb + 1]);
        PACK2F(b1p, bs[cb + 2], bs[cb + 3]);
        #pragma unroll
        for (int i = 0; i < 4; i++) {
            acc[i][0] = a0; acc[i][1] = a1; acc[i][2] = b0; acc[i][3] = b1p;
        }
    }

    #pragma unroll 4
    for (int k = 0; k < D; k++) {
        ulonglong2 wa = *(const ulonglong2*)&Ws[k][ca];
        ulonglong2 wb = *(const ulonglong2*)&Ws[k][cb];
        #pragma unroll
        for (int i = 0; i < 4; i++) {
            u64 xx; PACK_DUP(xx, Xs[r0 + i][k]);
            FMA2(acc[i][0], xx, wa.x, acc[i][0]);
            FMA2(acc[i][1], xx, wa.y, acc[i][1]);
            FMA2(acc[i][2], xx, wb.x, acc[i][2]);
            FMA2(acc[i][3], xx, wb.y, acc[i][3]);
        }
    }

    #pragma unroll
    for (int i = 0; i < 4; i++) {
        int row = row_base + r0 + i;
        if (row < N_NODES) {
            float lo, hi;
            float4 va, vb;
            UNPACK2F(lo, hi, acc[i][0]); va.x = leaky(lo); va.y = leaky(hi);
            UNPACK2F(lo, hi, acc[i][1]); va.z = leaky(lo); va.w = leaky(hi);
            UNPACK2F(lo, hi, acc[i][2]); vb.x = leaky(lo); vb.y = leaky(hi);
            UNPACK2F(lo, hi, acc[i][3]); vb.z = leaky(lo); vb.w = leaky(hi);
            *(float4*)(out + (long long)row * D + ca) = va;
            *(float4*)(out + (long long)row * D + cb) = vb;
        }
    }
}

// ---------------------------------------------------------------------------
// launch — 3 kernels
// ---------------------------------------------------------------------------
extern "C" void kernel_launch(void* const* d_in, const int* in_sizes, int n_in,
                              void* d_out, int out_size) {
    const float* x   = (const float*)d_in[0];
    const int*   ei  = (const int*)d_in[1];      // int32 (JAX downcasts int64)
    const float* eps = (const float*)d_in[2];
    const float* W1  = (const float*)d_in[3];
    const float* b1  = (const float*)d_in[4];
    const float* W2  = (const float*)d_in[5];
    const float* b2  = (const float*)d_in[6];
    float* out = (float*)d_out;

    float* agg;    cudaGetSymbolAddress((void**)&agg,    g_agg);
    int*   cnt;    cudaGetSymbolAddress((void**)&cnt,    g_count);
    int*   bucket; cudaGetSymbolAddress((void**)&bucket, g_bucket);

    const int4* src4 = (const int4*)ei;
    const int4* dst4 = (const int4*)(ei + N_EDGES);
    const int EQ = N_EDGES / 4;

    fill_kernel<<<(EQ + 255) / 256, 256>>>(src4, dst4, cnt, bucket);      // #0
    gather_kernel<<<(N_NODES + 7) / 8, 256>>>((const float2*)x, eps,      // #1
                                              cnt, bucket, (float2*)agg);
    mlp_kernel<<<(N_NODES + MLP_ROWS - 1) / MLP_ROWS, MLP_THREADS>>>(     // #2
        agg, W1, b1, W2, b2, out);
}

// round 13
// speedup vs baseline: 1.7264x; 1.3606x over previous
#include <cuda_runtime.h>
#include <cuda_bf16.h>
#include <cstdint>

#define N_NODES 100000
#define N_EDGES 1000000
#define D 64

typedef unsigned long long u64;

// ---------------------------------------------------------------------------
// Scratch. g_count starts zero (device globals zero-init) and every
// kernel_launch leaves it zero (scan resets it) -> no zero kernel.
// ---------------------------------------------------------------------------
__device__ float g_agg[N_NODES * D];
__device__ int   g_count[N_NODES];
__device__ int   g_off[N_NODES];
__device__ int   g_end[N_NODES];
__device__ int   g_cur[N_NODES];
__device__ int   g_src[N_EDGES];
__device__ int   g_base;

// ---------------------------------------------------------------------------
// K0: histogram of dst — 4 edges per thread (int4 load, 4 indep atomics)
// ---------------------------------------------------------------------------
__global__ void hist_kernel(const int4* __restrict__ dst4,
                            int* __restrict__ cnt,
                            int* __restrict__ base) {
    int t = blockIdx.x * blockDim.x + threadIdx.x;
    if (t == 0) *base = 0;
    if (t < N_EDGES / 4) {
        int4 d = dst4[t];
        if ((unsigned)d.x < N_NODES) atomicAdd(&cnt[d.x], 1);
        if ((unsigned)d.y < N_NODES) atomicAdd(&cnt[d.y], 1);
        if ((unsigned)d.z < N_NODES) atomicAdd(&cnt[d.z], 1);
        if ((unsigned)d.w < N_NODES) atomicAdd(&cnt[d.w], 1);
    }
}

// ---------------------------------------------------------------------------
// K1: block scan + atomic base -> off/end/cur; reset cnt.
// ---------------------------------------------------------------------------
#define SCAN_BLK 256
#define N_SBLKS ((N_NODES + SCAN_BLK - 1) / SCAN_BLK)

__global__ __launch_bounds__(SCAN_BLK)
void scan_atomic_kernel(int* __restrict__ cnt, int* __restrict__ off,
                        int* __restrict__ endp, int* __restrict__ cur,
                        int* __restrict__ base) {
    __shared__ int sm[SCAN_BLK];
    __shared__ int sbase;
    int i = blockIdx.x * SCAN_BLK + threadIdx.x;
    int t = threadIdx.x;
    int v = (i < N_NODES) ? cnt[i] : 0;
    sm[t] = v;
    for (int ofs = 1; ofs < SCAN_BLK; ofs <<= 1) {
        __syncthreads();
        int u = (t >= ofs) ? sm[t - ofs] : 0;
        __syncthreads();
        sm[t] += u;
    }
    __syncthreads();
    if (t == SCAN_BLK - 1) sbase = atomicAdd(base, sm[SCAN_BLK - 1]);
    __syncthreads();
    if (i < N_NODES) {
        int incl = sbase + sm[t];
        int st = incl - v;
        off[i]  = st;
        cur[i]  = st;
        endp[i] = incl;
        cnt[i]  = 0;
    }
}

// ---------------------------------------------------------------------------
// K2: fill CSR src lists — 4 edges per thread (2x int4 loads, 4 indep chains)
// ---------------------------------------------------------------------------
__global__ void fill_kernel(const int4* __restrict__ src4,
                            const int4* __restrict__ dst4,
                            int* __restrict__ cur,
                            int* __restrict__ csr_src) {
    int t = blockIdx.x * blockDim.x + threadIdx.x;
    if (t < N_EDGES / 4) {
        int4 s = src4[t];
        int4 d = dst4[t];
        if ((unsigned)s.x < N_NODES && (unsigned)d.x < N_NODES)
            csr_src[atomicAdd(&cur[d.x], 1)] = s.x;
        if ((unsigned)s.y < N_NODES && (unsigned)d.y < N_NODES)
            csr_src[atomicAdd(&cur[d.y], 1)] = s.y;
        if ((unsigned)s.z < N_NODES && (unsigned)d.z < N_NODES)
            csr_src[atomicAdd(&cur[d.z], 1)] = s.z;
        if ((unsigned)s.w < N_NODES && (unsigned)d.w < N_NODES)
            csr_src[atomicAdd(&cur[d.w], 1)] = s.w;
    }
}

// ---------------------------------------------------------------------------
// K3: gather + fused (1+eps)*x, float4 edition.
// One warp per node. half = lane>>4, hl = lane&15: lane owns float4 col hl,
// half-warp 0/1 process neighbors j+0 / j+1 of each pair -> one LDG.128
// serves 2 neighbors; 2 pairs in flight per unrolled step. Halves combined
// at the end via shfl_xor(16).
// ---------------------------------------------------------------------------
__global__ __launch_bounds__(256)
void gather_kernel(const float4* __restrict__ x4,
                   const float* __restrict__ eps,
                   const int* __restrict__ off,
                   const int* __restrict__ endp,
                   const int* __restrict__ csr_src,
                   float4* __restrict__ agg4) {
    int warp = (blockIdx.x * blockDim.x + threadIdx.x) >> 5;
    int lane = threadIdx.x & 31;
    if (warp >= N_NODES) return;
    const int half = lane >> 4;     // 0 or 1
    const int hl   = lane & 15;     // float4 index within row

    float4 acc = make_float4(0.f, 0.f, 0.f, 0.f);
    if (half == 0) {
        float s = 1.0f + *eps;
        float4 v = x4[(unsigned)warp * 16u + hl];
        acc.x = s * v.x; acc.y = s * v.y; acc.z = s * v.z; acc.w = s * v.w;
    }

    int start = off[warp];
    int end   = endp[warp];

    for (int base = start; base < end; base += 32) {
        int n = min(32, end - base);
        int myidx = (lane < n) ? csr_src[base + lane] : 0;
        for (int j = 0; j < n; j += 4) {
            // pair A: neighbors j, j+1; pair B: neighbors j+2, j+3
            int sA = __shfl_sync(0xffffffffu, myidx, j + half);
            int sB = __shfl_sync(0xffffffffu, myidx, j + 2 + half);
            bool vA = (j + half) < n;
            bool vB = (j + 2 + half) < n;
            if (vA) {
                float4 a = x4[(unsigned)sA * 16u + hl];
                acc.x += a.x; acc.y += a.y; acc.z += a.z; acc.w += a.w;
            }
            if (vB) {
                float4 b = x4[(unsigned)sB * 16u + hl];
                acc.x += b.x; acc.y += b.y; acc.z += b.z; acc.w += b.w;
            }
        }
    }

    // combine halves
    acc.x += __shfl_xor_sync(0xffffffffu, acc.x, 16);
    acc.y += __shfl_xor_sync(0xffffffffu, acc.y, 16);
    acc.z += __shfl_xor_sync(0xffffffffu, acc.z, 16);
    acc.w += __shfl_xor_sync(0xffffffffu, acc.w, 16);

    if (half == 0)
        agg4[(unsigned)warp * 16u + hl] = acc;
}

// ---------------------------------------------------------------------------
// K4: fused 2-layer MLP (conflict-free quads, FMA2, 4 rows/thread)
// ---------------------------------------------------------------------------
#define MLP_ROWS 64
#define MLP_THREADS 128
#define XS_STRIDE 66

__device__ __forceinline__ float leaky(float v) {
    return fmaxf(v, 0.01f * v);
}

#define FMA2(d, a, b, c) \
    asm("fma.rn.f32x2 %0, %1, %2, %3;" : "=l"(d) : "l"(a), "l"(b), "l"(c))
#define PACK_DUP(out, f) \
    asm("mov.b64 %0, {%1, %1};" : "=l"(out) : "r"(__float_as_uint(f)))
#define PACK2F(out, lo, hi) \
    asm("mov.b64 %0, {%1, %2};" : "=l"(out) : "r"(__float_as_uint(lo)), "r"(__float_as_uint(hi)))
#define UNPACK2F(lo, hi, in) \
    { unsigned _l, _h; asm("mov.b64 {%0, %1}, %2;" : "=r"(_l), "=r"(_h) : "l"(in)); \
      lo = __uint_as_float(_l); hi = __uint_as_float(_h); }

__global__ __launch_bounds__(MLP_THREADS)
void mlp_kernel(const float* __restrict__ agg,
                const float* __restrict__ W1, const float* __restrict__ b1,
                const float* __restrict__ W2, const float* __restrict__ b2,
                float* __restrict__ out) {
    __shared__ float Xs[MLP_ROWS][XS_STRIDE];
    __shared__ float Ws[D][D];
    __shared__ float bs[D];

    const int tid = threadIdx.x;
    const int cg  = tid & 7;
    const int rg  = tid >> 3;
    const int row_base = blockIdx.x * MLP_ROWS;
    const int r0 = rg * 4;
    const int ca = cg * 4;
    const int cb = 32 + cg * 4;

    {
        const float2* src = (const float2*)(agg + (long long)row_base * D);
        for (int idx = tid; idx < MLP_ROWS * (D / 2); idx += MLP_THREADS) {
            int r = idx >> 5;
            int p = idx & 31;
            float2 v;
            if (row_base + r < N_NODES) v = src[r * 32 + p];
            else { v.x = 0.f; v.y = 0.f; }
            Xs[r][p * 2]     = v.x;
            Xs[r][p * 2 + 1] = v.y;
        }
    }
    {
        const float4* w = (const float4*)W1;
        float4* ws = (float4*)&Ws[0][0];
        for (int idx = tid; idx < D * D / 4; idx += MLP_THREADS) ws[idx] = w[idx];
        if (tid < D) bs[tid] = b1[tid];
    }
    __syncthreads();

    u64 acc[4][4];
    {
        u64 a0, a1, b0, b1p;
        PACK2F(a0, bs[ca],     bs[ca + 1]);
        PACK2F(a1, bs[ca + 2], bs[ca + 3]);
        PACK2F(b0, bs[cb],     bs[cb + 1]);
        PACK2F(b1p, bs[cb + 2], bs[cb + 3]);
        #pragma unroll
        for (int i = 0; i < 4; i++) {
            acc[i][0] = a0; acc[i][1] = a1; acc[i][2] = b0; acc[i][3] = b1p;
        }
    }

    #pragma unroll 4
    for (int k = 0; k < D; k++) {
        ulonglong2 wa = *(const ulonglong2*)&Ws[k][ca];
        ulonglong2 wb = *(const ulonglong2*)&Ws[k][cb];
        #pragma unroll
        for (int i = 0; i < 4; i++) {
            u64 xx; PACK_DUP(xx, Xs[r0 + i][k]);
            FMA2(acc[i][0], xx, wa.x, acc[i][0]);
            FMA2(acc[i][1], xx, wa.y, acc[i][1]);
            FMA2(acc[i][2], xx, wb.x, acc[i][2]);
            FMA2(acc[i][3], xx, wb.y, acc[i][3]);
        }
    }
    __syncthreads();

    #pragma unroll
    for (int i = 0; i < 4; i++) {
        float lo, hi;
        UNPACK2F(lo, hi, acc[i][0]); Xs[r0 + i][ca]     = leaky(lo); Xs[r0 + i][ca + 1] = leaky(hi);
        UNPACK2F(lo, hi, acc[i][1]); Xs[r0 + i][ca + 2] = leaky(lo); Xs[r0 + i][ca + 3] = leaky(hi);
        UNPACK2F(lo, hi, acc[i][2]); Xs[r0 + i][cb]     = leaky(lo); Xs[r0 + i][cb + 1] = leaky(hi);
        UNPACK2F(lo, hi, acc[i][3]); Xs[r0 + i][cb + 2] = leaky(lo); Xs[r0 + i][cb + 3] = leaky(hi);
    }

    {
        const float4* w = (const float4*)W2;
        float4* ws = (float4*)&Ws[0][0];
        for (int idx = tid; idx < D * D / 4; idx += MLP_THREADS) ws[idx] = w[idx];
        if (tid < D) bs[tid] = b2[tid];
    }
    __syncthreads();

    {
        u64 a0, a1, b0, b1p;
        PACK2F(a0, bs[ca],     bs[ca + 1]);
        PACK2F(a1, bs[ca + 2], bs[ca + 3]);
        PACK2F(b0, bs[cb],     bs[cb + 1]);
        PACK2F(b1p, bs[cb + 2], bs[cb + 3]);
        #pragma unroll
        for (int i = 0; i < 4; i++) {
            acc[i][0] = a0; acc[i][1] = a1; acc[i][2] = b0; acc[i][3] = b1p;
        }
    }

    #pragma unroll 4
    for (int k = 0; k < D; k++) {
        ulonglong2 wa = *(const ulonglong2*)&Ws[k][ca];
        ulonglong2 wb = *(const ulonglong2*)&Ws[k][cb];
        #pragma unroll
        for (int i = 0; i < 4; i++) {
            u64 xx; PACK_DUP(xx, Xs[r0 + i][k]);
            FMA2(acc[i][0], xx, wa.x, acc[i][0]);
            FMA2(acc[i][1], xx, wa.y, acc[i][1]);
            FMA2(acc[i][2], xx, wb.x, acc[i][2]);
            FMA2(acc[i][3], xx, wb.y, acc[i][3]);
        }
    }

    #pragma unroll
    for (int i = 0; i < 4; i++) {
        int row = row_base + r0 + i;
        if (row < N_NODES) {
            float lo, hi;
            float4 va, vb;
            UNPACK2F(lo, hi, acc[i][0]); va.x = leaky(lo); va.y = leaky(hi);
            UNPACK2F(lo, hi, acc[i][1]); va.z = leaky(lo); va.w = leaky(hi);
            UNPACK2F(lo, hi, acc[i][2]); vb.x = leaky(lo); vb.y = leaky(hi);
            UNPACK2F(lo, hi, acc[i][3]); vb.z = leaky(lo); vb.w = leaky(hi);
            *(float4*)(out + (long long)row * D + ca) = va;
            *(float4*)(out + (long long)row * D + cb) = vb;
        }
    }
}

// ---------------------------------------------------------------------------
// launch
// ---------------------------------------------------------------------------
extern "C" void kernel_launch(void* const* d_in, const int* in_sizes, int n_in,
                              void* d_out, int out_size) {
    const float* x   = (const float*)d_in[0];
    const int*   ei  = (const int*)d_in[1];      // int32 (JAX downcasts int64)
    const float* eps = (const float*)d_in[2];
    const float* W1  = (const float*)d_in[3];
    const float* b1  = (const float*)d_in[4];
    const float* W2  = (const float*)d_in[5];
    const float* b2  = (const float*)d_in[6];
    float* out = (float*)d_out;

    float* agg;  cudaGetSymbolAddress((void**)&agg,  g_agg);
    int*   cnt;  cudaGetSymbolAddress((void**)&cnt,  g_count);
    int*   off;  cudaGetSymbolAddress((void**)&off,  g_off);
    int*   endp; cudaGetSymbolAddress((void**)&endp, g_end);
    int*   cur;  cudaGetSymbolAddress((void**)&cur,  g_cur);
    int*   csrs; cudaGetSymbolAddress((void**)&csrs, g_src);
    int*   base; cudaGetSymbolAddress((void**)&base, g_base);

    const int4* src4 = (const int4*)ei;
    const int4* dst4 = (const int4*)(ei + N_EDGES);
    const int EQ = N_EDGES / 4;

    hist_kernel<<<(EQ + 255) / 256, 256>>>(dst4, cnt, base);               // #0
    scan_atomic_kernel<<<N_SBLKS, SCAN_BLK>>>(cnt, off, endp, cur, base);  // #1
    fill_kernel<<<(EQ + 255) / 256, 256>>>(src4, dst4, cur, csrs);         // #2
    gather_kernel<<<(N_NODES + 7) / 8, 256>>>((const float4*)x, eps,       // #3
                                              off, endp, csrs, (float4*)agg);
    mlp_kernel<<<(N_NODES + MLP_ROWS - 1) / MLP_ROWS, MLP_THREADS>>>(      // #4
        agg, W1, b1, W2, b2, out);
}

// round 14
// speedup vs baseline: 1.8746x; 1.0858x over previous
#include <cuda_runtime.h>
#include <cuda_bf16.h>
#include <cstdint>

#define N_NODES 100000
#define N_EDGES 1000000
#define D 64

typedef unsigned long long u64;

// ---------------------------------------------------------------------------
// Scratch. g_count starts zero (device globals zero-init) and every
// kernel_launch leaves it zero (scan resets it).
// ---------------------------------------------------------------------------
__device__ float g_agg[N_NODES * D];
__device__ int   g_count[N_NODES];
__device__ int   g_off[N_NODES];
__device__ int   g_end[N_NODES];
__device__ int   g_cur[N_NODES];
__device__ int   g_src[N_EDGES];
__device__ int   g_base;

// ---------------------------------------------------------------------------
// K0: histogram of dst — 4 edges per thread
// ---------------------------------------------------------------------------
__global__ void hist_kernel(const int4* __restrict__ dst4,
                            int* __restrict__ cnt,
                            int* __restrict__ base) {
    int t = blockIdx.x * blockDim.x + threadIdx.x;
    if (t == 0) *base = 0;
    if (t < N_EDGES / 4) {
        int4 d = dst4[t];
        if ((unsigned)d.x < N_NODES) atomicAdd(&cnt[d.x], 1);
        if ((unsigned)d.y < N_NODES) atomicAdd(&cnt[d.y], 1);
        if ((unsigned)d.z < N_NODES) atomicAdd(&cnt[d.z], 1);
        if ((unsigned)d.w < N_NODES) atomicAdd(&cnt[d.w], 1);
    }
}

// ---------------------------------------------------------------------------
// K1: block scan + atomic base -> off/end/cur; reset cnt.
// ---------------------------------------------------------------------------
#define SCAN_BLK 256
#define N_SBLKS ((N_NODES + SCAN_BLK - 1) / SCAN_BLK)

__global__ __launch_bounds__(SCAN_BLK)
void scan_atomic_kernel(int* __restrict__ cnt, int* __restrict__ off,
                        int* __restrict__ endp, int* __restrict__ cur,
                        int* __restrict__ base) {
    __shared__ int sm[SCAN_BLK];
    __shared__ int sbase;
    int i = blockIdx.x * SCAN_BLK + threadIdx.x;
    int t = threadIdx.x;
    int v = (i < N_NODES) ? cnt[i] : 0;
    sm[t] = v;
    for (int ofs = 1; ofs < SCAN_BLK; ofs <<= 1) {
        __syncthreads();
        int u = (t >= ofs) ? sm[t - ofs] : 0;
        __syncthreads();
        sm[t] += u;
    }
    __syncthreads();
    if (t == SCAN_BLK - 1) sbase = atomicAdd(base, sm[SCAN_BLK - 1]);
    __syncthreads();
    if (i < N_NODES) {
        int incl = sbase + sm[t];
        int st = incl - v;
        off[i]  = st;
        cur[i]  = st;
        endp[i] = incl;
        cnt[i]  = 0;
    }
}

// ---------------------------------------------------------------------------
// K2: fill CSR src lists — 4 edges per thread
// ---------------------------------------------------------------------------
__global__ void fill_kernel(const int4* __restrict__ src4,
                            const int4* __restrict__ dst4,
                            int* __restrict__ cur,
                            int* __restrict__ csr_src) {
    int t = blockIdx.x * blockDim.x + threadIdx.x;
    if (t < N_EDGES / 4) {
        int4 s = src4[t];
        int4 d = dst4[t];
        if ((unsigned)s.x < N_NODES && (unsigned)d.x < N_NODES)
            csr_src[atomicAdd(&cur[d.x], 1)] = s.x;
        if ((unsigned)s.y < N_NODES && (unsigned)d.y < N_NODES)
            csr_src[atomicAdd(&cur[d.y], 1)] = s.y;
        if ((unsigned)s.z < N_NODES && (unsigned)d.z < N_NODES)
            csr_src[atomicAdd(&cur[d.z], 1)] = s.z;
        if ((unsigned)s.w < N_NODES && (unsigned)d.w < N_NODES)
            csr_src[atomicAdd(&cur[d.w], 1)] = s.w;
    }
}

// ---------------------------------------------------------------------------
// K3: gather + fused (1+eps)*x, float4 edition (measured 33us; unchanged).
// ---------------------------------------------------------------------------
__global__ __launch_bounds__(256)
void gather_kernel(const float4* __restrict__ x4,
                   const float* __restrict__ eps,
                   const int* __restrict__ off,
                   const int* __restrict__ endp,
                   const int* __restrict__ csr_src,
                   float4* __restrict__ agg4) {
    int warp = (blockIdx.x * blockDim.x + threadIdx.x) >> 5;
    int lane = threadIdx.x & 31;
    if (warp >= N_NODES) return;
    const int half = lane >> 4;
    const int hl   = lane & 15;

    float4 acc = make_float4(0.f, 0.f, 0.f, 0.f);
    if (half == 0) {
        float s = 1.0f + *eps;
        float4 v = x4[(unsigned)warp * 16u + hl];
        acc.x = s * v.x; acc.y = s * v.y; acc.z = s * v.z; acc.w = s * v.w;
    }

    int start = off[warp];
    int end   = endp[warp];

    for (int base = start; base < end; base += 32) {
        int n = min(32, end - base);
        int myidx = (lane < n) ? csr_src[base + lane] : 0;
        for (int j = 0; j < n; j += 4) {
            int sA = __shfl_sync(0xffffffffu, myidx, j + half);
            int sB = __shfl_sync(0xffffffffu, myidx, j + 2 + half);
            bool vA = (j + half) < n;
            bool vB = (j + 2 + half) < n;
            if (vA) {
                float4 a = x4[(unsigned)sA * 16u + hl];
                acc.x += a.x; acc.y += a.y; acc.z += a.z; acc.w += a.w;
            }
            if (vB) {
                float4 b = x4[(unsigned)sB * 16u + hl];
                acc.x += b.x; acc.y += b.y; acc.z += b.z; acc.w += b.w;
            }
        }
    }

    acc.x += __shfl_xor_sync(0xffffffffu, acc.x, 16);
    acc.y += __shfl_xor_sync(0xffffffffu, acc.y, 16);
    acc.z += __shfl_xor_sync(0xffffffffu, acc.z, 16);
    acc.w += __shfl_xor_sync(0xffffffffu, acc.w, 16);

    if (half == 0)
        agg4[(unsigned)warp * 16u + hl] = acc;
}

// ---------------------------------------------------------------------------
// K4: fused 2-layer MLP via tf32 mma.sync (m16n8k8).
// 128 threads = 4 warps; warp w owns rows [16w, 16w+16).
// Weights staged into fragment-ordered smem (Bf): per-MMA B = one LDS.64.
// A-fragments read from Xs (4 scalar LDS + cvt.rna.tf32 per k-tile).
// Layer-1 C gets leaky in regs -> written back to warp-local Xs rows.
// ---------------------------------------------------------------------------
#define MLP_ROWS 64
#define MLP_THREADS 128
#define XS_STRIDE 66

__device__ __forceinline__ float leaky(float v) {
    return fmaxf(v, 0.01f * v);
}

#define CVT_TF32(d, s) asm("cvt.rna.tf32.f32 %0, %1;" : "=r"(d) : "f"(s))

#define MMA_TF32(c0, c1, c2, c3, a0, a1, a2, a3, b0, b1) \
    asm("mma.sync.aligned.m16n8k8.row.col.f32.tf32.tf32.f32 " \
        "{%0,%1,%2,%3}, {%4,%5,%6,%7}, {%8,%9}, {%0,%1,%2,%3};" \
        : "+f"(c0), "+f"(c1), "+f"(c2), "+f"(c3) \
        : "r"(a0), "r"(a1), "r"(a2), "r"(a3), "r"(b0), "r"(b1))

__global__ __launch_bounds__(MLP_THREADS)
void mlp_kernel(const float* __restrict__ agg,
                const float* __restrict__ W1, const float* __restrict__ b1,
                const float* __restrict__ W2, const float* __restrict__ b2,
                float* __restrict__ out) {
    __shared__ float Xs[MLP_ROWS][XS_STRIDE];   // 16.9 KB (fp32 activations)
    __shared__ float Bf[8 * 8 * 32 * 2];        // 16 KB (tf32 B fragments)
    __shared__ float bs[D];

    const int tid  = threadIdx.x;
    const int w    = tid >> 5;        // warp 0..3
    const int l    = tid & 31;        // lane
    const int row_base = blockIdx.x * MLP_ROWS;

    // --- stage X tile (coalesced, fp32) ---
    {
        const float2* src = (const float2*)(agg + (long long)row_base * D);
        for (int idx = tid; idx < MLP_ROWS * (D / 2); idx += MLP_THREADS) {
            int r = idx >> 5;
            int p = idx & 31;
            float2 v;
            if (row_base + r < N_NODES) v = src[r * 32 + p];
            else { v.x = 0.f; v.y = 0.f; }
            Xs[r][p * 2]     = v.x;
            Xs[r][p * 2 + 1] = v.y;
        }
    }
    // --- stage W1 into fragment order (tf32), b1 ---
    {
        for (int idx = tid; idx < D * D; idx += MLP_THREADS) {
            int k = idx >> 6, n = idx & 63;
            unsigned tv; CVT_TF32(tv, W1[idx]);
            int slot = ((((k >> 3) * 8 + (n >> 3)) * 32 +
                        (((n & 7) << 2) | (k & 3))) << 1) | ((k & 7) >> 2);
            Bf[slot] = __uint_as_float(tv);
        }
        if (tid < D) bs[tid] = b1[tid];
    }
    __syncthreads();

    const int ar  = 16 * w + (l >> 2);   // A fragment row (and C row)
    const int ac  = l & 3;               // A fragment col within k-tile
    const float2* Bf2 = (const float2*)Bf;

    float c[8][4];

    // ================= layer 1 =================
    #pragma unroll
    for (int nt = 0; nt < 8; nt++) {
        float bb0 = bs[8 * nt + 2 * (l & 3)];
        float bb1 = bs[8 * nt + 2 * (l & 3) + 1];
        c[nt][0] = bb0; c[nt][1] = bb1; c[nt][2] = bb0; c[nt][3] = bb1;
    }

    #pragma unroll
    for (int kt = 0; kt < 8; kt++) {
        unsigned a0, a1, a2, a3;
        int kc = 8 * kt + ac;
        CVT_TF32(a0, Xs[ar][kc]);
        CVT_TF32(a1, Xs[ar + 8][kc]);
        CVT_TF32(a2, Xs[ar][kc + 4]);
        CVT_TF32(a3, Xs[ar + 8][kc + 4]);
        #pragma unroll
        for (int nt = 0; nt < 8; nt++) {
            float2 b = Bf2[(kt * 8 + nt) * 32 + l];
            MMA_TF32(c[nt][0], c[nt][1], c[nt][2], c[nt][3],
                     a0, a1, a2, a3,
                     __float_as_uint(b.x), __float_as_uint(b.y));
        }
    }

    // leaky + write back to this warp's own Xs rows (no cross-warp access)
    #pragma unroll
    for (int nt = 0; nt < 8; nt++) {
        int col0 = 8 * nt + 2 * (l & 3);
        Xs[ar][col0]         = leaky(c[nt][0]);
        Xs[ar][col0 + 1]     = leaky(c[nt][1]);
        Xs[ar + 8][col0]     = leaky(c[nt][2]);
        Xs[ar + 8][col0 + 1] = leaky(c[nt][3]);
    }
    __syncthreads();   // all warps done reading Bf(W1) & writing Xs

    // --- stage W2 into fragment order, b2 ---
    {
        for (int idx = tid; idx < D * D; idx += MLP_THREADS) {
            int k = idx >> 6, n = idx & 63;
            unsigned tv; CVT_TF32(tv, W2[idx]);
            int slot = ((((k >> 3) * 8 + (n >> 3)) * 32 +
                        (((n & 7) << 2) | (k & 3))) << 1) | ((k & 7) >> 2);
            Bf[slot] = __uint_as_float(tv);
        }
        if (tid < D) bs[tid] = b2[tid];
    }
    __syncthreads();

    // ================= layer 2 =================
    #pragma unroll
    for (int nt = 0; nt < 8; nt++) {
        float bb0 = bs[8 * nt + 2 * (l & 3)];
        float bb1 = bs[8 * nt + 2 * (l & 3) + 1];
        c[nt][0] = bb0; c[nt][1] = bb1; c[nt][2] = bb0; c[nt][3] = bb1;
    }

    #pragma unroll
    for (int kt = 0; kt < 8; kt++) {
        unsigned a0, a1, a2, a3;
        int kc = 8 * kt + ac;
        CVT_TF32(a0, Xs[ar][kc]);
        CVT_TF32(a1, Xs[ar + 8][kc]);
        CVT_TF32(a2, Xs[ar][kc + 4]);
        CVT_TF32(a3, Xs[ar + 8][kc + 4]);
        #pragma unroll
        for (int nt = 0; nt < 8; nt++) {
            float2 b = Bf2[(kt * 8 + nt) * 32 + l];
            MMA_TF32(c[nt][0], c[nt][1], c[nt][2], c[nt][3],
                     a0, a1, a2, a3,
                     __float_as_uint(b.x), __float_as_uint(b.y));
        }
    }

    // --- epilogue: leaky + float2 stores ---
    {
        int row0 = row_base + ar;
        int row1 = row0 + 8;
        #pragma unroll
        for (int nt = 0; nt < 8; nt++) {
            int col0 = 8 * nt + 2 * (l & 3);
            if (row0 < N_NODES) {
                float2 v; v.x = leaky(c[nt][0]); v.y = leaky(c[nt][1]);
                *(float2*)(out + (long long)row0 * D + col0) = v;
            }
            if (row1 < N_NODES) {
                float2 v; v.x = leaky(c[nt][2]); v.y = leaky(c[nt][3]);
                *(float2*)(out + (long long)row1 * D + col0) = v;
            }
        }
    }
}

// ---------------------------------------------------------------------------
// launch
// ---------------------------------------------------------------------------
extern "C" void kernel_launch(void* const* d_in, const int* in_sizes, int n_in,
                              void* d_out, int out_size) {
    const float* x   = (const float*)d_in[0];
    const int*   ei  = (const int*)d_in[1];      // int32 (JAX downcasts int64)
    const float* eps = (const float*)d_in[2];
    const float* W1  = (const float*)d_in[3];
    const float* b1  = (const float*)d_in[4];
    const float* W2  = (const float*)d_in[5];
    const float* b2  = (const float*)d_in[6];
    float* out = (float*)d_out;

    float* agg;  cudaGetSymbolAddress((void**)&agg,  g_agg);
    int*   cnt;  cudaGetSymbolAddress((void**)&cnt,  g_count);
    int*   off;  cudaGetSymbolAddress((void**)&off,  g_off);
    int*   endp; cudaGetSymbolAddress((void**)&endp, g_end);
    int*   cur;  cudaGetSymbolAddress((void**)&cur,  g_cur);
    int*   csrs; cudaGetSymbolAddress((void**)&csrs, g_src);
    int*   base; cudaGetSymbolAddress((void**)&base, g_base);

    const int4* src4 = (const int4*)ei;
    const int4* dst4 = (const int4*)(ei + N_EDGES);
    const int EQ = N_EDGES / 4;

    hist_kernel<<<(EQ + 255) / 256, 256>>>(dst4, cnt, base);               // #0
    scan_atomic_kernel<<<N_SBLKS, SCAN_BLK>>>(cnt, off, endp, cur, base);  // #1
    fill_kernel<<<(EQ + 255) / 256, 256>>>(src4, dst4, cur, csrs);         // #2
    gather_kernel<<<(N_NODES + 7) / 8, 256>>>((const float4*)x, eps,       // #3
                                              off, endp, csrs, (float4*)agg);
    mlp_kernel<<<(N_NODES + MLP_ROWS - 1) / MLP_ROWS, MLP_THREADS>>>(      // #4
        agg, W1, b1, W2, b2, out);
}

// round 15
// speedup vs baseline: 2.3170x; 1.2360x over previous
#include <cuda_runtime.h>
#include <cuda_bf16.h>
#include <cstdint>

#define N_NODES 100000
#define N_EDGES 1000000
#define D 64

typedef unsigned long long u64;

// ---------------------------------------------------------------------------
// Scratch. g_count starts zero (device globals zero-init) and every
// kernel_launch leaves it zero (scan resets it).
// ---------------------------------------------------------------------------
__device__ float g_agg[N_NODES * D];
__device__ int   g_count[N_NODES];
__device__ int   g_off[N_NODES];
__device__ int   g_end[N_NODES];
__device__ int   g_cur[N_NODES];
__device__ int   g_src[N_EDGES];
__device__ int   g_base;
__device__ float g_Wf1[D * D];      // fragment-ordered tf32 W1
__device__ float g_Wf2[D * D];      // fragment-ordered tf32 W2

#define CVT_TF32(d, s) asm("cvt.rna.tf32.f32 %0, %1;" : "=r"(d) : "f"(s))

// ---------------------------------------------------------------------------
// K-prep: one-time fragment-order + tf32 conversion of W1/W2.
// slot layout validated in R14 (rel_err 4.2e-4 pass).
// ---------------------------------------------------------------------------
__global__ void prep_kernel(const float* __restrict__ W1,
                            const float* __restrict__ W2,
                            float* __restrict__ Wf1,
                            float* __restrict__ Wf2) {
    int idx = blockIdx.x * blockDim.x + threadIdx.x;
    if (idx < D * D) {
        int k = idx >> 6, n = idx & 63;
        int slot = ((((k >> 3) * 8 + (n >> 3)) * 32 +
                    (((n & 7) << 2) | (k & 3))) << 1) | ((k & 7) >> 2);
        unsigned tv;
        CVT_TF32(tv, W1[idx]); Wf1[slot] = __uint_as_float(tv);
        CVT_TF32(tv, W2[idx]); Wf2[slot] = __uint_as_float(tv);
    }
}

// ---------------------------------------------------------------------------
// K0: histogram of dst — 4 edges per thread
// ---------------------------------------------------------------------------
__global__ void hist_kernel(const int4* __restrict__ dst4,
                            int* __restrict__ cnt,
                            int* __restrict__ base) {
    int t = blockIdx.x * blockDim.x + threadIdx.x;
    if (t == 0) *base = 0;
    if (t < N_EDGES / 4) {
        int4 d = dst4[t];
        if ((unsigned)d.x < N_NODES) atomicAdd(&cnt[d.x], 1);
        if ((unsigned)d.y < N_NODES) atomicAdd(&cnt[d.y], 1);
        if ((unsigned)d.z < N_NODES) atomicAdd(&cnt[d.z], 1);
        if ((unsigned)d.w < N_NODES) atomicAdd(&cnt[d.w], 1);
    }
}

// ---------------------------------------------------------------------------
// K1: block scan + atomic base -> off/end/cur; reset cnt.
// ---------------------------------------------------------------------------
#define SCAN_BLK 256
#define N_SBLKS ((N_NODES + SCAN_BLK - 1) / SCAN_BLK)

__global__ __launch_bounds__(SCAN_BLK)
void scan_atomic_kernel(int* __restrict__ cnt, int* __restrict__ off,
                        int* __restrict__ endp, int* __restrict__ cur,
                        int* __restrict__ base) {
    __shared__ int sm[SCAN_BLK];
    __shared__ int sbase;
    int i = blockIdx.x * SCAN_BLK + threadIdx.x;
    int t = threadIdx.x;
    int v = (i < N_NODES) ? cnt[i] : 0;
    sm[t] = v;
    for (int ofs = 1; ofs < SCAN_BLK; ofs <<= 1) {
        __syncthreads();
        int u = (t >= ofs) ? sm[t - ofs] : 0;
        __syncthreads();
        sm[t] += u;
    }
    __syncthreads();
    if (t == SCAN_BLK - 1) sbase = atomicAdd(base, sm[SCAN_BLK - 1]);
    __syncthreads();
    if (i < N_NODES) {
        int incl = sbase + sm[t];
        int st = incl - v;
        off[i]  = st;
        cur[i]  = st;
        endp[i] = incl;
        cnt[i]  = 0;
    }
}

// ---------------------------------------------------------------------------
// K2: fill CSR src lists — 4 edges per thread
// ---------------------------------------------------------------------------
__global__ void fill_kernel(const int4* __restrict__ src4,
                            const int4* __restrict__ dst4,
                            int* __restrict__ cur,
                            int* __restrict__ csr_src) {
    int t = blockIdx.x * blockDim.x + threadIdx.x;
    if (t < N_EDGES / 4) {
        int4 s = src4[t];
        int4 d = dst4[t];
        if ((unsigned)s.x < N_NODES && (unsigned)d.x < N_NODES)
            csr_src[atomicAdd(&cur[d.x], 1)] = s.x;
        if ((unsigned)s.y < N_NODES && (unsigned)d.y < N_NODES)
            csr_src[atomicAdd(&cur[d.y], 1)] = s.y;
        if ((unsigned)s.z < N_NODES && (unsigned)d.z < N_NODES)
            csr_src[atomicAdd(&cur[d.z], 1)] = s.z;
        if ((unsigned)s.w < N_NODES && (unsigned)d.w < N_NODES)
            csr_src[atomicAdd(&cur[d.w], 1)] = s.w;
    }
}

// ---------------------------------------------------------------------------
// K3: gather + fused (1+eps)*x — HALF-WARP per node.
// node = 2*warp + (lane>>4); hl = lane&15 owns float4 column hl.
// Every neighbor LDG.128, the self load, and the store are full-warp 512B
// (2 rows for 2 nodes). Width-16 shfl broadcasts; warp-uniform loop bound
// via __reduce_max_sync; unroll-4 -> 4 independent row loads in flight.
// Grid covers exactly N_NODES (even), so no bounds checks.
// ---------------------------------------------------------------------------
__global__ __launch_bounds__(256)
void gather_kernel(const float4* __restrict__ x4,
                   const float* __restrict__ eps,
                   const int* __restrict__ off,
                   const int* __restrict__ endp,
                   const int* __restrict__ csr_src,
                   float4* __restrict__ agg4) {
    int gw   = (blockIdx.x * blockDim.x + threadIdx.x) >> 5;
    int lane = threadIdx.x & 31;
    int half = lane >> 4;
    int hl   = lane & 15;
    int node = gw * 2 + half;

    float s = 1.0f + *eps;
    int start = off[node];
    int deg   = endp[node] - start;

    float4 acc;
    {
        float4 v = x4[(unsigned)node * 16u + hl];
        acc.x = s * v.x; acc.y = s * v.y; acc.z = s * v.z; acc.w = s * v.w;
    }

    int degmax = __reduce_max_sync(0xffffffffu, deg);

    for (int b = 0; b < degmax; b += 16) {
        int nb    = deg - b;                 // per-half remaining (may be <=0)
        int nbmax = min(16, degmax - b);
        int myidx = (hl < nb) ? csr_src[start + b + hl] : 0;
        for (int j = 0; j < nbmax; j += 4) {
            int s0 = __shfl_sync(0xffffffffu, myidx, j,     16);
            int s1 = __shfl_sync(0xffffffffu, myidx, j + 1, 16);
            int s2 = __shfl_sync(0xffffffffu, myidx, j + 2, 16);
            int s3 = __shfl_sync(0xffffffffu, myidx, j + 3, 16);
            if (j < nb) {
                float4 a = x4[(unsigned)s0 * 16u + hl];
                acc.x += a.x; acc.y += a.y; acc.z += a.z; acc.w += a.w;
            }
            if (j + 1 < nb) {
                float4 a = x4[(unsigned)s1 * 16u + hl];
                acc.x += a.x; acc.y += a.y; acc.z += a.z; acc.w += a.w;
            }
            if (j + 2 < nb) {
                float4 a = x4[(unsigned)s2 * 16u + hl];
                acc.x += a.x; acc.y += a.y; acc.z += a.z; acc.w += a.w;
            }
            if (j + 3 < nb) {
                float4 a = x4[(unsigned)s3 * 16u + hl];
                acc.x += a.x; acc.y += a.y; acc.z += a.z; acc.w += a.w;
            }
        }
    }
    agg4[(unsigned)node * 16u + hl] = acc;
}

// ---------------------------------------------------------------------------
// K4: fused 2-layer MLP via tf32 mma.sync — weights pre-fragmented in global.
// 128 threads = 4 warps; warp w owns rows [16w, 16w+16). Only smem = Xs.
// B fragments: LDG.64 from g_Wf* (warp-uniform 256B/MMA, L1-hot).
// One __syncthreads (Xs staging); layer boundary is warp-local (__syncwarp).
// ---------------------------------------------------------------------------
#define MLP_ROWS 64
#define MLP_THREADS 128
#define XS_STRIDE 66

__device__ __forceinline__ float leaky(float v) {
    return fmaxf(v, 0.01f * v);
}

#define MMA_TF32(c0, c1, c2, c3, a0, a1, a2, a3, b0, b1) \
    asm("mma.sync.aligned.m16n8k8.row.col.f32.tf32.tf32.f32 " \
        "{%0,%1,%2,%3}, {%4,%5,%6,%7}, {%8,%9}, {%0,%1,%2,%3};" \
        : "+f"(c0), "+f"(c1), "+f"(c2), "+f"(c3) \
        : "r"(a0), "r"(a1), "r"(a2), "r"(a3), "r"(b0), "r"(b1))

__global__ __launch_bounds__(MLP_THREADS)
void mlp_kernel(const float* __restrict__ agg,
                const float* __restrict__ Wf1, const float* __restrict__ b1,
                const float* __restrict__ Wf2, const float* __restrict__ b2,
                float* __restrict__ out) {
    __shared__ float Xs[MLP_ROWS][XS_STRIDE];   // 16.9 KB — only smem

    const int tid = threadIdx.x;
    const int w   = tid >> 5;
    const int l   = tid & 31;
    const int row_base = blockIdx.x * MLP_ROWS;

    // --- stage X tile (coalesced fp32) ---
    {
        const float2* src = (const float2*)(agg + (long long)row_base * D);
        for (int idx = tid; idx < MLP_ROWS * (D / 2); idx += MLP_THREADS) {
            int r = idx >> 5;
            int p = idx & 31;
            float2 v;
            if (row_base + r < N_NODES) v = src[r * 32 + p];
            else { v.x = 0.f; v.y = 0.f; }
            Xs[r][p * 2]     = v.x;
            Xs[r][p * 2 + 1] = v.y;
        }
    }
    __syncthreads();

    const int ar = 16 * w + (l >> 2);
    const int ac = l & 3;
    const float2* B1 = (const float2*)Wf1;
    const float2* B2 = (const float2*)Wf2;

    float c[8][4];

    // ================= layer 1 =================
    #pragma unroll
    for (int nt = 0; nt < 8; nt++) {
        float bb0 = b1[8 * nt + 2 * ac];
        float bb1 = b1[8 * nt + 2 * ac + 1];
        c[nt][0] = bb0; c[nt][1] = bb1; c[nt][2] = bb0; c[nt][3] = bb1;
    }

    #pragma unroll
    for (int kt = 0; kt < 8; kt++) {
        unsigned a0, a1, a2, a3;
        int kc = 8 * kt + ac;
        CVT_TF32(a0, Xs[ar][kc]);
        CVT_TF32(a1, Xs[ar + 8][kc]);
        CVT_TF32(a2, Xs[ar][kc + 4]);
        CVT_TF32(a3, Xs[ar + 8][kc + 4]);
        #pragma unroll
        for (int nt = 0; nt < 8; nt++) {
            float2 b = B1[(kt * 8 + nt) * 32 + l];
            MMA_TF32(c[nt][0], c[nt][1], c[nt][2], c[nt][3],
                     a0, a1, a2, a3,
                     __float_as_uint(b.x), __float_as_uint(b.y));
        }
    }

    // leaky + write back to warp-local Xs rows
    #pragma unroll
    for (int nt = 0; nt < 8; nt++) {
        int col0 = 8 * nt + 2 * ac;
        Xs[ar][col0]         = leaky(c[nt][0]);
        Xs[ar][col0 + 1]     = leaky(c[nt][1]);
        Xs[ar + 8][col0]     = leaky(c[nt][2]);
        Xs[ar + 8][col0 + 1] = leaky(c[nt][3]);
    }
    __syncwarp();   // cross-lane within warp only

    // ================= layer 2 =================
    #pragma unroll
    for (int nt = 0; nt < 8; nt++) {
        float bb0 = b2[8 * nt + 2 * ac];
        float bb1 = b2[8 * nt + 2 * ac + 1];
        c[nt][0] = bb0; c[nt][1] = bb1; c[nt][2] = bb0; c[nt][3] = bb1;
    }

    #pragma unroll
    for (int kt = 0; kt < 8; kt++) {
        unsigned a0, a1, a2, a3;
        int kc = 8 * kt + ac;
        CVT_TF32(a0, Xs[ar][kc]);
        CVT_TF32(a1, Xs[ar + 8][kc]);
        CVT_TF32(a2, Xs[ar][kc + 4]);
        CVT_TF32(a3, Xs[ar + 8][kc + 4]);
        #pragma unroll
        for (int nt = 0; nt < 8; nt++) {
            float2 b = B2[(kt * 8 + nt) * 32 + l];
            MMA_TF32(c[nt][0], c[nt][1], c[nt][2], c[nt][3],
                     a0, a1, a2, a3,
                     __float_as_uint(b.x), __float_as_uint(b.y));
        }
    }

    // --- epilogue ---
    {
        int row0 = row_base + ar;
        int row1 = row0 + 8;
        #pragma unroll
        for (int nt = 0; nt < 8; nt++) {
            int col0 = 8 * nt + 2 * ac;
            if (row0 < N_NODES) {
                float2 v; v.x = leaky(c[nt][0]); v.y = leaky(c[nt][1]);
                *(float2*)(out + (long long)row0 * D + col0) = v;
            }
            if (row1 < N_NODES) {
                float2 v; v.x = leaky(c[nt][2]); v.y = leaky(c[nt][3]);
                *(float2*)(out + (long long)row1 * D + col0) = v;
            }
        }
    }
}

// ---------------------------------------------------------------------------
// launch
// ---------------------------------------------------------------------------
extern "C" void kernel_launch(void* const* d_in, const int* in_sizes, int n_in,
                              void* d_out, int out_size) {
    const float* x   = (const float*)d_in[0];
    const int*   ei  = (const int*)d_in[1];      // int32 (JAX downcasts int64)
    const float* eps = (const float*)d_in[2];
    const float* W1  = (const float*)d_in[3];
    const float* b1  = (const float*)d_in[4];
    const float* W2  = (const float*)d_in[5];
    const float* b2  = (const float*)d_in[6];
    float* out = (float*)d_out;

    float* agg;  cudaGetSymbolAddress((void**)&agg,  g_agg);
    int*   cnt;  cudaGetSymbolAddress((void**)&cnt,  g_count);
    int*   off;  cudaGetSymbolAddress((void**)&off,  g_off);
    int*   endp; cudaGetSymbolAddress((void**)&endp, g_end);
    int*   cur;  cudaGetSymbolAddress((void**)&cur,  g_cur);
    int*   csrs; cudaGetSymbolAddress((void**)&csrs, g_src);
    int*   base; cudaGetSymbolAddress((void**)&base, g_base);
    float* wf1;  cudaGetSymbolAddress((void**)&wf1,  g_Wf1);
    float* wf2;  cudaGetSymbolAddress((void**)&wf2,  g_Wf2);

    const int4* src4 = (const int4*)ei;
    const int4* dst4 = (const int4*)(ei + N_EDGES);
    const int EQ = N_EDGES / 4;

    prep_kernel<<<(D * D + 255) / 256, 256>>>(W1, W2, wf1, wf2);           // #0
    hist_kernel<<<(EQ + 255) / 256, 256>>>(dst4, cnt, base);               // #1
    scan_atomic_kernel<<<N_SBLKS, SCAN_BLK>>>(cnt, off, endp, cur, base);  // #2
    fill_kernel<<<(EQ + 255) / 256, 256>>>(src4, dst4, cur, csrs);         // #3
    gather_kernel<<<N_NODES / 16, 256>>>((const float4*)x, eps,            // #4
                                         off, endp, csrs, (float4*)agg);
    mlp_kernel<<<(N_NODES + MLP_ROWS - 1) / MLP_ROWS, MLP_THREADS>>>(      // #5
        agg, wf1, b1, wf2, b2, out);
}